// round 15
// baseline (speedup 1.0000x reference)
#include <cuda_runtime.h>
#include <cuda_fp16.h>
#include <math.h>
#include <cstdint>

#define Bb   16
#define Tt   4096
#define Cc   512
#define Ee   256
#define NE   1024
#define NTOK (Bb*Tt)

// ---- scratch (static device memory) ----
// embed fragments (f16): [cgp(4)][ks(16)][tn(32)][lane(32)] float4 = {b0h,b1h,b0l,b1l}
__device__ __align__(16) float g_ef[(size_t)NE * Ee];
// proj-weight fragments (f16): [ks(32)][tn(32)][lane(32)] float4
__device__ __align__(16) float g_wf[(size_t)Ee * Cc];
__device__ float  g_enorm[NE];
__device__ int    g_hist[NE];
__device__ double g_mse;            // sum of d2_min over tokens

// ---------------- helpers ----------------
__device__ __forceinline__ uint32_t smem_u32(const void* p) {
    uint32_t a;
    asm("{ .reg .u64 t; cvta.to.shared.u64 t, %1; cvt.u32.u64 %0, t; }" : "=r"(a) : "l"(p));
    return a;
}
// split two floats into packed f16x2 hi + f16x2 lo
__device__ __forceinline__ uint32_t packsplit(float x0, float x1, uint32_t& lo) {
    __half h0 = __float2half_rn(x0);
    __half l0 = __float2half_rn(x0 - __half2float(h0));
    __half h1 = __float2half_rn(x1);
    __half l1 = __float2half_rn(x1 - __half2float(h1));
    __half2 hh = __halves2half2(h0, h1), ll = __halves2half2(l0, l1);
    lo = *(uint32_t*)&ll;
    return *(uint32_t*)&hh;
}
__device__ __forceinline__ void mmaf16(float* d, uint32_t a0, uint32_t a1,
                                       uint32_t a2, uint32_t a3,
                                       uint32_t b0, uint32_t b1) {
    asm volatile(
        "mma.sync.aligned.m16n8k16.row.col.f32.f16.f16.f32 "
        "{%0,%1,%2,%3}, {%4,%5,%6,%7}, {%8,%9}, {%0,%1,%2,%3};"
        : "+f"(d[0]), "+f"(d[1]), "+f"(d[2]), "+f"(d[3])
        : "r"(a0), "r"(a1), "r"(a2), "r"(a3), "r"(b0), "r"(b1));
}
__device__ __forceinline__ void cp16(uint32_t s, const void* g) {
    asm volatile("cp.async.cg.shared.global [%0], [%1], 16;" :: "r"(s), "l"(g));
}
#define CP_COMMIT() asm volatile("cp.async.commit_group;" ::: "memory")
#define CP_WAIT1()  asm volatile("cp.async.wait_group 1;" ::: "memory")
#define CP_WAIT0()  asm volatile("cp.async.wait_group 0;" ::: "memory")

// ---------------------------------------------------------------
// prep: blocks [0,1024): embed fragments + ||e||^2 + hist/mse zero
//       blocks [1024,1536): proj-weight fragments
// ---------------------------------------------------------------
__global__ void k_prep(const float* __restrict__ embed, const float* __restrict__ w) {
    if (blockIdx.x < NE) {
        int c = blockIdx.x;                 // code 0..1023
        int e = threadIdx.x;                // k 0..255
        float v = embed[(size_t)c * Ee + e];
        __half h = __float2half_rn(v);
        __half l = __float2half_rn(v - __half2float(h));
        int cgp = c >> 8, cl = c & 255, tn = cl >> 3, qq = cl & 7;
        int ks = e >> 4, r = e & 15, kq = (r >> 1) & 3, odd = r & 1, b1f = r >> 3;
        int lane = qq * 4 + kq;
        size_t f4 = (((size_t)cgp * 16 + ks) * 32 + tn) * 32 + lane;
        __half* hp = (__half*)g_ef;
        hp[f4 * 8 + b1f * 2 + odd]     = h;
        hp[f4 * 8 + 4 + b1f * 2 + odd] = l;

        float s = v * v;
        __shared__ float red[8];
        for (int o = 16; o > 0; o >>= 1) s += __shfl_down_sync(0xffffffffu, s, o);
        if ((e & 31) == 0) red[e >> 5] = s;
        __syncthreads();
        if (e == 0) {
            float t = 0.f;
            #pragma unroll
            for (int i = 0; i < 8; i++) t += red[i];
            g_enorm[c] = t;
            g_hist[c]  = 0;
            if (c == 0) g_mse = 0.0;
        }
    } else {
        int c = blockIdx.x - NE;            // 0..511 (k dim)
        int e = threadIdx.x;                // 0..255 (n dim)
        float v = w[(size_t)e * Cc + c];
        __half h = __float2half_rn(v);
        __half l = __float2half_rn(v - __half2float(h));
        int ks = c >> 4, r = c & 15, kq = (r >> 1) & 3, odd = r & 1, b1f = r >> 3;
        int tn = e >> 3, qq = e & 7;
        int lane = qq * 4 + kq;
        size_t f4 = ((size_t)ks * 32 + tn) * 32 + lane;
        __half* hp = (__half*)g_wf;
        hp[f4 * 8 + b1f * 2 + odd]     = h;
        hp[f4 * 8 + 4 + b1f * 2 + odd] = l;
    }
}

// ---------------------------------------------------------------
// FUSED proj + dist + output: CTA = 64 tokens, 256 threads, occ 2
// Phase 1 (proj): 32 k16 W-chunks (3-stage ring), A staged in [0,8K);
//   x fragments written to [0,64K) afterward
// Phase 2 (dist): 64 k16 B-chunks (3-stage ring) over 1024 codes, argmin
// Phase 3 (out):  gather embed[idx], smem transpose, coalesced store
// smem: A frags [0,64K) | ring [64K,112K)
// ---------------------------------------------------------------
#define MAIN_DYN (65536 + 3 * 16384)
__global__ void __launch_bounds__(256, 2)
k_main(const float* __restrict__ in, const float* __restrict__ bias,
       const float* __restrict__ embed, float* __restrict__ out) {
    extern __shared__ char dyn[];
    __shared__ float sXn[64];

    int tid  = threadIdx.x;
    int lane = tid & 31, wid = tid >> 5;
    int wm   = wid >> 2, wn = wid & 3;
    int q    = lane >> 2, kq = lane & 3;
    int g    = blockIdx.x;                           // 64-token group
    int n0   = g * 64;
    int b    = n0 >> 12, t0 = n0 & 4095;
    const float* inb = in + (size_t)b * Cc * Tt + t0;
    uint32_t dynu  = smem_u32(dyn);
    uint32_t ringu = dynu + 65536;

    if (tid < 64) sXn[tid] = 0.f;

    // ================= PHASE 1: projection =================
    {
        // W ring (3-stage) at ring[0,48K); A-stage (2 bufs, 8KB) at dyn[0,8K)
        float*  stAf = (float*)dyn;
        float4* stA4 = (float4*)dyn;
        int akq = tid & 3, aq = (tid >> 2) & 7, atm = (tid >> 5) & 3, khalf = tid >> 7;

        #define ISSUE_W(ch) do {                                                      \
            const char* _s = (const char*)((const float4*)g_wf + (size_t)(ch)*1024);  \
            uint32_t _d = ringu + (uint32_t)((ch) % 3) * 16384;                       \
            for (int i = tid; i < 1024; i += 256)                                     \
                cp16(_d + (uint32_t)i * 16, _s + (size_t)i * 16);                     \
            CP_COMMIT();                                                              \
        } while (0)

        #define LDG_A(ch, v) do {                                                     \
            const float* _p = inb + (size_t)((ch) * 16 + khalf * 8 + 2 * akq) * Tt    \
                                  + atm * 16 + aq;                                    \
            (v)[0] = _p[0];  (v)[1] = _p[Tt];                                         \
            (v)[2] = _p[8];  (v)[3] = _p[Tt + 8];                                     \
        } while (0)

        #define STS_A(buf, v) do {                                                    \
            uint32_t _l0, _l1;                                                        \
            uint32_t _h0 = packsplit((v)[0], (v)[1], _l0);                            \
            uint32_t _h1 = packsplit((v)[2], (v)[3], _l1);                            \
            int _o = (buf) * 1024 + (atm * 32 + aq * 4 + akq) * 4 + khalf * 2;        \
            *(uint2*)&stAf[_o]       = make_uint2(_h0, _h1);                          \
            *(uint2*)&stAf[_o + 512] = make_uint2(_l0, _l1);                          \
        } while (0)

        {
            float v[4];
            LDG_A(0, v);
            STS_A(0, v);
        }
        ISSUE_W(0);
        ISSUE_W(1);

        float acc[2][8][4];
        #pragma unroll
        for (int a = 0; a < 2; a++)
            #pragma unroll
            for (int bb = 0; bb < 8; bb++)
                #pragma unroll
                for (int cix = 0; cix < 4; cix++) acc[a][bb][cix] = 0.f;

        for (int ch = 0; ch < 32; ch++) {
            if (ch < 31) CP_WAIT1(); else CP_WAIT0();
            __syncthreads();             // publishes stA[ch&1] + W(ch); retires W(ch-1)
            if (ch + 2 < 32) ISSUE_W(ch + 2);   // stage (ch+2)%3: disjoint from read stage
            float v[4];
            if (ch < 31) LDG_A(ch + 1, v);

            const float4* W4 = (const float4*)(dyn + 65536 + (ch % 3) * 16384);
            uint32_t aH[2][4], aL[2][4];
            #pragma unroll
            for (int mt = 0; mt < 2; mt++) {
                int tmg = wm * 2 + mt;
                float4 h4 = stA4[(ch & 1) * 256 + tmg * 32 + lane];
                float4 l4 = stA4[(ch & 1) * 256 + 128 + tmg * 32 + lane];
                aH[mt][0] = __float_as_uint(h4.x); aH[mt][1] = __float_as_uint(h4.y);
                aH[mt][2] = __float_as_uint(h4.z); aH[mt][3] = __float_as_uint(h4.w);
                aL[mt][0] = __float_as_uint(l4.x); aL[mt][1] = __float_as_uint(l4.y);
                aL[mt][2] = __float_as_uint(l4.z); aL[mt][3] = __float_as_uint(l4.w);
            }
            #pragma unroll
            for (int nt = 0; nt < 8; nt++) {
                int tng = wn * 8 + nt;
                float4 bf = W4[tng * 32 + lane];
                uint32_t bh0 = __float_as_uint(bf.x), bh1 = __float_as_uint(bf.y);
                uint32_t bl0 = __float_as_uint(bf.z), bl1 = __float_as_uint(bf.w);
                #pragma unroll
                for (int mt = 0; mt < 2; mt++) {
                    mmaf16(acc[mt][nt], aH[mt][0], aH[mt][1], aH[mt][2], aH[mt][3], bh0, bh1);
                    mmaf16(acc[mt][nt], aH[mt][0], aH[mt][1], aH[mt][2], aH[mt][3], bl0, bl1);
                    mmaf16(acc[mt][nt], aL[mt][0], aL[mt][1], aL[mt][2], aL[mt][3], bh0, bh1);
                }
            }
            if (ch < 31) STS_A((ch + 1) & 1, v);
        }

        // epilogue: bias, ||x||^2, x fragments -> smem A region [0,64K)
        __syncthreads();                 // all stA/W reads retired; A region writable
        float4* xf4 = (float4*)dyn;
        #pragma unroll
        for (int mt = 0; mt < 2; mt++) {
            int tmg = wm * 2 + mt;
            float xnq = 0.f, xnq8 = 0.f;
            #pragma unroll
            for (int ntp = 0; ntp < 4; ntp++) {   // nt pairs (even, odd)
                int ntE = ntp * 2, ntO = ntp * 2 + 1;
                int eE = wn * 64 + ntE * 8 + 2 * kq;
                int eO = wn * 64 + ntO * 8 + 2 * kq;
                float bE0 = __ldg(&bias[eE]),     bE1 = __ldg(&bias[eE + 1]);
                float bO0 = __ldg(&bias[eO]),     bO1 = __ldg(&bias[eO + 1]);
                float x0 = acc[mt][ntE][0] + bE0;
                float x1 = acc[mt][ntE][1] + bE1;
                float x2 = acc[mt][ntE][2] + bE0;
                float x3 = acc[mt][ntE][3] + bE1;
                float y0 = acc[mt][ntO][0] + bO0;
                float y1 = acc[mt][ntO][1] + bO1;
                float y2 = acc[mt][ntO][2] + bO0;
                float y3 = acc[mt][ntO][3] + bO1;
                xnq  += x0 * x0 + x1 * x1 + y0 * y0 + y1 * y1;
                xnq8 += x2 * x2 + x3 * x3 + y2 * y2 + y3 * y3;
                int ks = wn * 4 + ntp;
                uint32_t l0, l1, l2, l3;
                uint32_t h0 = packsplit(x0, x1, l0);
                uint32_t h1 = packsplit(x2, x3, l1);
                uint32_t h2 = packsplit(y0, y1, l2);
                uint32_t h3 = packsplit(y2, y3, l3);
                int idx = (ks * 4 + tmg) * 32 + lane;
                xf4[idx]        = make_float4(__uint_as_float(h0), __uint_as_float(h1),
                                              __uint_as_float(h2), __uint_as_float(h3));
                xf4[2048 + idx] = make_float4(__uint_as_float(l0), __uint_as_float(l1),
                                              __uint_as_float(l2), __uint_as_float(l3));
            }
            xnq  += __shfl_xor_sync(0xffffffffu, xnq, 1);
            xnq  += __shfl_xor_sync(0xffffffffu, xnq, 2);
            xnq8 += __shfl_xor_sync(0xffffffffu, xnq8, 1);
            xnq8 += __shfl_xor_sync(0xffffffffu, xnq8, 2);
            if (kq == 0) {
                int tl = wm * 32 + mt * 16 + q;
                atomicAdd(&sXn[tl], xnq);
                atomicAdd(&sXn[tl + 8], xnq8);
            }
        }
    }

    // ================= PHASE 2: distance + argmin =================
    const float4* smA = (const float4*)dyn;

    #define ISSUE(cc) do {                                                        \
        int _cgp = (cc) >> 4, _ks = (cc) & 15;                                    \
        const char* _s = (const char*)((const float4*)g_ef +                      \
                          ((size_t)(_cgp * 16 + _ks)) * 1024);                    \
        uint32_t _d = ringu + (uint32_t)((cc) % 3) * 16384;                       \
        for (int i = tid; i < 1024; i += 256)                                     \
            cp16(_d + (uint32_t)i * 16, _s + (size_t)i * 16);                     \
        CP_COMMIT();                                                              \
    } while (0)

    ISSUE(0);
    ISSUE(1);

    float acc[2][8][4];
    #pragma unroll
    for (int a = 0; a < 2; a++)
        #pragma unroll
        for (int b2 = 0; b2 < 8; b2++)
            #pragma unroll
            for (int c = 0; c < 4; c++) acc[a][b2][c] = 0.f;
    float bestv[4]; int besti[4];
    #pragma unroll
    for (int s = 0; s < 4; s++) { bestv[s] = 3.0e38f; besti[s] = 0; }

    for (int cc = 0; cc < 64; cc++) {
        if (cc + 1 < 64) CP_WAIT1(); else CP_WAIT0();
        __syncthreads();                 // publishes buf[cc] (+A frags on cc==0)
        if (cc + 2 < 64) ISSUE(cc + 2);
        const float4* B4 = (const float4*)(dyn + 65536 + (cc % 3) * 16384);
        int ks = cc & 15;
        uint32_t aH[2][4], aL[2][4];
        #pragma unroll
        for (int tm2 = 0; tm2 < 2; tm2++) {
            int tmg = wm * 2 + tm2;
            float4 h4 = smA[(ks * 4 + tmg) * 32 + lane];
            float4 l4 = smA[2048 + (ks * 4 + tmg) * 32 + lane];
            aH[tm2][0] = __float_as_uint(h4.x); aH[tm2][1] = __float_as_uint(h4.y);
            aH[tm2][2] = __float_as_uint(h4.z); aH[tm2][3] = __float_as_uint(h4.w);
            aL[tm2][0] = __float_as_uint(l4.x); aL[tm2][1] = __float_as_uint(l4.y);
            aL[tm2][2] = __float_as_uint(l4.z); aL[tm2][3] = __float_as_uint(l4.w);
        }
        #pragma unroll
        for (int tn = 0; tn < 8; tn++) {
            int tng = wn * 8 + tn;
            float4 bf = B4[tng * 32 + lane];
            uint32_t bh0 = __float_as_uint(bf.x), bh1 = __float_as_uint(bf.y);
            uint32_t bl0 = __float_as_uint(bf.z), bl1 = __float_as_uint(bf.w);
            #pragma unroll
            for (int tm2 = 0; tm2 < 2; tm2++) {
                mmaf16(acc[tm2][tn], aH[tm2][0], aH[tm2][1], aH[tm2][2], aH[tm2][3], bh0, bh1);
                mmaf16(acc[tm2][tn], aH[tm2][0], aH[tm2][1], aH[tm2][2], aH[tm2][3], bl0, bl1);
                mmaf16(acc[tm2][tn], aL[tm2][0], aL[tm2][1], aL[tm2][2], aL[tm2][3], bh0, bh1);
            }
        }
        if (ks == 15) {
            int cgp = cc >> 4;
            #pragma unroll
            for (int tn = 0; tn < 8; tn++) {
                int tng = wn * 8 + tn;
                int nb = cgp * 256 + tng * 8 + 2 * kq;
                float e0v = __ldg(&g_enorm[nb]);
                float e1v = __ldg(&g_enorm[nb + 1]);
                #pragma unroll
                for (int tm2 = 0; tm2 < 2; tm2++) {
                    float s00 = fmaf(-2.0f, acc[tm2][tn][0], e0v);
                    float s01 = fmaf(-2.0f, acc[tm2][tn][1], e1v);
                    float s10 = fmaf(-2.0f, acc[tm2][tn][2], e0v);
                    float s11 = fmaf(-2.0f, acc[tm2][tn][3], e1v);
                    int s0 = tm2 * 2, s1 = tm2 * 2 + 1;
                    if (s00 < bestv[s0]) { bestv[s0] = s00; besti[s0] = nb; }
                    if (s01 < bestv[s0]) { bestv[s0] = s01; besti[s0] = nb + 1; }
                    if (s10 < bestv[s1]) { bestv[s1] = s10; besti[s1] = nb; }
                    if (s11 < bestv[s1]) { bestv[s1] = s11; besti[s1] = nb + 1; }
                    acc[tm2][tn][0] = 0.f; acc[tm2][tn][1] = 0.f;
                    acc[tm2][tn][2] = 0.f; acc[tm2][tn][3] = 0.f;
                }
            }
        }
    }
    __syncthreads();                     // compute done; reuse B ring
    float* redv = (float*)(dyn + 65536);            // 64*4 floats
    int*   redi = (int*)(dyn + 65536 + 1024);       // 64*4 ints
    float* lred = (float*)(dyn + 65536 + 2048);     // 2 floats
    int*   sidx = (int*)(dyn + 65536 + 4096);       // 64 ints

    #pragma unroll
    for (int s = 0; s < 4; s++) {
        float v = bestv[s]; int bi = besti[s];
        #pragma unroll
        for (int off = 1; off <= 2; off <<= 1) {
            float ov = __shfl_xor_sync(0xffffffffu, v, off);
            int   oi = __shfl_xor_sync(0xffffffffu, bi, off);
            if (ov < v || (ov == v && oi < bi)) { v = ov; bi = oi; }
        }
        if ((lane & 3) == 0) {
            int row = wm * 32 + (s >> 1) * 16 + (s & 1) * 8 + q;
            redv[row * 4 + wn] = v;
            redi[row * 4 + wn] = bi;
        }
    }
    __syncthreads();
    float myd2 = 0.f;
    if (tid < 64) {
        float v = redv[tid * 4]; int bi = redi[tid * 4];
        #pragma unroll
        for (int j = 1; j < 4; j++) {
            float ov = redv[tid * 4 + j]; int oi = redi[tid * 4 + j];
            if (ov < v || (ov == v && oi < bi)) { v = ov; bi = oi; }
        }
        sidx[tid] = bi;
        atomicAdd(&g_hist[bi], 1);
        myd2 = sXn[tid] + v;                   // ||x||^2 + (||e||^2 - 2x.e)
    }
    for (int o = 16; o > 0; o >>= 1) myd2 += __shfl_down_sync(0xffffffffu, myd2, o);
    if ((tid & 31) == 0 && wid < 2) lred[wid] = myd2;
    __syncthreads();                     // sidx + lred published; redv/redi dead
    if (tid == 0) atomicAdd(&g_mse, (double)(lred[0] + lred[1]));

    // ================= PHASE 3: output gather + transpose =================
    // tbuf: [t(64)][e(256)] stride 257 floats (65792 B; overruns only dead redv)
    float* tbuf = (float*)dyn;
    {
        const float4* e4p = (const float4*)embed;
        for (int i = tid; i < 4096; i += 256) {
            int t = i >> 6, c4 = i & 63;
            float4 v = e4p[(size_t)sidx[t] * 64 + c4];
            float* d = tbuf + t * 257 + c4 * 4;
            d[0] = v.x; d[1] = v.y; d[2] = v.z; d[3] = v.w;
        }
    }
    __syncthreads();
    {
        float* ob = out + (size_t)b * Ee * Tt + t0;
        int t = tid & 63, e0 = tid >> 6;
        #pragma unroll 8
        for (int r = 0; r < 64; r++) {
            int e = r * 4 + e0;
            ob[(size_t)e * Tt + t] = tbuf[t * 257 + e];
        }
    }
}

// ---------------------------------------------------------------
// tail scalars
// ---------------------------------------------------------------
__global__ void k_tail(float* __restrict__ out) {
    __shared__ float red[32];
    int tid = threadIdx.x;                     // 1024
    float p = (float)g_hist[tid] / 65536.0f;
    float term = -p * logf(p + 1e-10f);
    for (int o = 16; o > 0; o >>= 1) term += __shfl_down_sync(0xffffffffu, term, o);
    if ((tid & 31) == 0) red[tid >> 5] = term;
    __syncthreads();
    const size_t base = (size_t)Bb * Ee * Tt;
    if (tid == 0) {
        float lp = 0.f;
        #pragma unroll
        for (int i = 0; i < 32; i++) lp += red[i];
        out[base + 0]  = (float)(1.25 * (g_mse / (double)((size_t)NTOK * Ee)));
        out[base + 17] = lp;
    }
    if (tid < 16) out[base + 1 + tid] = (float)(log(1024.0) * 4096.0);
}

// ---------------------------------------------------------------
extern "C" void kernel_launch(void* const* d_in, const int* in_sizes, int n_in,
                              void* d_out, int out_size) {
    const float* inputs = (const float*)d_in[0];   // [16, 512, 4096]
    const float* proj_w = (const float*)d_in[1];   // [256, 512]
    const float* proj_b = (const float*)d_in[2];   // [256]
    const float* embed  = (const float*)d_in[3];   // [1024, 256]
    float* out = (float*)d_out;

    cudaFuncSetAttribute(k_main, cudaFuncAttributeMaxDynamicSharedMemorySize, MAIN_DYN);

    k_prep<<<NE + Cc, 256>>>(embed, proj_w);
    k_main<<<NTOK / 64, 256, MAIN_DYN>>>(inputs, proj_b, embed, out);
    k_tail<<<1, 1024>>>(out);
}

// round 16
// speedup vs baseline: 1.0574x; 1.0574x over previous
#include <cuda_runtime.h>
#include <cuda_fp16.h>
#include <math.h>
#include <cstdint>

#define Bb   16
#define Tt   4096
#define Cc   512
#define Ee   256
#define NE   1024
#define NTOK (Bb*Tt)

// ---- scratch (static device memory) ----
// embed fragments (f16): [cgp(4)][ks(16)][tn(32)][lane(32)] float4 = {b0h,b1h,b0l,b1l}
__device__ __align__(16) float g_ef[(size_t)NE * Ee];
// proj-weight fragments (f16): [ks(32)][tn(32)][lane(32)] float4
__device__ __align__(16) float g_wf[(size_t)Ee * Cc];
__device__ float  g_enorm[NE];
__device__ int    g_idx[NTOK];
__device__ int    g_hist[NE];
__device__ double g_mse;            // sum of d2_min over tokens

// ---------------- helpers ----------------
__device__ __forceinline__ uint32_t smem_u32(const void* p) {
    uint32_t a;
    asm("{ .reg .u64 t; cvta.to.shared.u64 t, %1; cvt.u32.u64 %0, t; }" : "=r"(a) : "l"(p));
    return a;
}
// split two floats into packed f16x2 hi + f16x2 lo
__device__ __forceinline__ uint32_t packsplit(float x0, float x1, uint32_t& lo) {
    __half h0 = __float2half_rn(x0);
    __half l0 = __float2half_rn(x0 - __half2float(h0));
    __half h1 = __float2half_rn(x1);
    __half l1 = __float2half_rn(x1 - __half2float(h1));
    __half2 hh = __halves2half2(h0, h1), ll = __halves2half2(l0, l1);
    lo = *(uint32_t*)&ll;
    return *(uint32_t*)&hh;
}
__device__ __forceinline__ void mmaf16(float* d, uint32_t a0, uint32_t a1,
                                       uint32_t a2, uint32_t a3,
                                       uint32_t b0, uint32_t b1) {
    asm volatile(
        "mma.sync.aligned.m16n8k16.row.col.f32.f16.f16.f32 "
        "{%0,%1,%2,%3}, {%4,%5,%6,%7}, {%8,%9}, {%0,%1,%2,%3};"
        : "+f"(d[0]), "+f"(d[1]), "+f"(d[2]), "+f"(d[3])
        : "r"(a0), "r"(a1), "r"(a2), "r"(a3), "r"(b0), "r"(b1));
}
__device__ __forceinline__ void cp16(uint32_t s, const void* g) {
    asm volatile("cp.async.cg.shared.global [%0], [%1], 16;" :: "r"(s), "l"(g));
}
#define CP_COMMIT() asm volatile("cp.async.commit_group;" ::: "memory")
#define CP_WAIT1()  asm volatile("cp.async.wait_group 1;" ::: "memory")
#define CP_WAIT0()  asm volatile("cp.async.wait_group 0;" ::: "memory")

// ---------------------------------------------------------------
// prep: blocks [0,1024): embed fragments + ||e||^2 + hist/mse zero
//       blocks [1024,1536): proj-weight fragments
// ---------------------------------------------------------------
__global__ void k_prep(const float* __restrict__ embed, const float* __restrict__ w) {
    if (blockIdx.x < NE) {
        int c = blockIdx.x;                 // code 0..1023
        int e = threadIdx.x;                // k 0..255
        float v = embed[(size_t)c * Ee + e];
        __half h = __float2half_rn(v);
        __half l = __float2half_rn(v - __half2float(h));
        int cgp = c >> 8, cl = c & 255, tn = cl >> 3, qq = cl & 7;
        int ks = e >> 4, r = e & 15, kq = (r >> 1) & 3, odd = r & 1, b1f = r >> 3;
        int lane = qq * 4 + kq;
        size_t f4 = (((size_t)cgp * 16 + ks) * 32 + tn) * 32 + lane;
        __half* hp = (__half*)g_ef;
        hp[f4 * 8 + b1f * 2 + odd]     = h;
        hp[f4 * 8 + 4 + b1f * 2 + odd] = l;

        float s = v * v;
        __shared__ float red[8];
        for (int o = 16; o > 0; o >>= 1) s += __shfl_down_sync(0xffffffffu, s, o);
        if ((e & 31) == 0) red[e >> 5] = s;
        __syncthreads();
        if (e == 0) {
            float t = 0.f;
            #pragma unroll
            for (int i = 0; i < 8; i++) t += red[i];
            g_enorm[c] = t;
            g_hist[c]  = 0;
            if (c == 0) g_mse = 0.0;
        }
    } else {
        int c = blockIdx.x - NE;            // 0..511 (k dim)
        int e = threadIdx.x;                // 0..255 (n dim)
        float v = w[(size_t)e * Cc + c];
        __half h = __float2half_rn(v);
        __half l = __float2half_rn(v - __half2float(h));
        int ks = c >> 4, r = c & 15, kq = (r >> 1) & 3, odd = r & 1, b1f = r >> 3;
        int tn = e >> 3, qq = e & 7;
        int lane = qq * 4 + kq;
        size_t f4 = ((size_t)ks * 32 + tn) * 32 + lane;
        __half* hp = (__half*)g_wf;
        hp[f4 * 8 + b1f * 2 + odd]     = h;
        hp[f4 * 8 + 4 + b1f * 2 + odd] = l;
    }
}

// ---------------------------------------------------------------
// FUSED proj + dist: CTA = 64 tokens, 256 threads (8 warps 2m x 4n), occ 2
// Phase 1 (proj): 32 k16 W-chunks (3-stage ring), A staged in [0,8K) of the
//   A region (dead until epilogue); x fragments written to [0,64K) afterward
// Phase 2 (dist): 64 k16 B-chunks (3-stage ring) over 1024 codes, argmin
// smem: A frags [0,64K) | ring [64K,112K)
// ---------------------------------------------------------------
#define MAIN_DYN (65536 + 3 * 16384)
__global__ void __launch_bounds__(256, 2)
k_main(const float* __restrict__ in, const float* __restrict__ bias) {
    extern __shared__ char dyn[];
    __shared__ float sXn[64];

    int tid  = threadIdx.x;
    int lane = tid & 31, wid = tid >> 5;
    int wm   = wid >> 2, wn = wid & 3;
    int q    = lane >> 2, kq = lane & 3;
    int g    = blockIdx.x;                           // 64-token group
    int n0   = g * 64;
    int b    = n0 >> 12, t0 = n0 & 4095;
    const float* inb = in + (size_t)b * Cc * Tt + t0;
    uint32_t dynu  = smem_u32(dyn);
    uint32_t ringu = dynu + 65536;

    if (tid < 64) sXn[tid] = 0.f;

    // ================= PHASE 1: projection =================
    {
        // W ring (3-stage) at ring[0,48K); A-stage (2 bufs, 8KB) at dyn[0,8K)
        float*  stAf = (float*)dyn;
        float4* stA4 = (float4*)dyn;
        int akq = tid & 3, aq = (tid >> 2) & 7, atm = (tid >> 5) & 3, khalf = tid >> 7;

        #define ISSUE_W(ch) do {                                                      \
            const char* _s = (const char*)((const float4*)g_wf + (size_t)(ch)*1024);  \
            uint32_t _d = ringu + (uint32_t)((ch) % 3) * 16384;                       \
            for (int i = tid; i < 1024; i += 256)                                     \
                cp16(_d + (uint32_t)i * 16, _s + (size_t)i * 16);                     \
            CP_COMMIT();                                                              \
        } while (0)

        #define LDG_A(ch, v) do {                                                     \
            const float* _p = inb + (size_t)((ch) * 16 + khalf * 8 + 2 * akq) * Tt    \
                                  + atm * 16 + aq;                                    \
            (v)[0] = _p[0];  (v)[1] = _p[Tt];                                         \
            (v)[2] = _p[8];  (v)[3] = _p[Tt + 8];                                     \
        } while (0)

        #define STS_A(buf, v) do {                                                    \
            uint32_t _l0, _l1;                                                        \
            uint32_t _h0 = packsplit((v)[0], (v)[1], _l0);                            \
            uint32_t _h1 = packsplit((v)[2], (v)[3], _l1);                            \
            int _o = (buf) * 1024 + (atm * 32 + aq * 4 + akq) * 4 + khalf * 2;        \
            *(uint2*)&stAf[_o]       = make_uint2(_h0, _h1);                          \
            *(uint2*)&stAf[_o + 512] = make_uint2(_l0, _l1);                          \
        } while (0)

        {
            float v[4];
            LDG_A(0, v);
            STS_A(0, v);
        }
        ISSUE_W(0);
        ISSUE_W(1);

        float acc[2][8][4];
        #pragma unroll
        for (int a = 0; a < 2; a++)
            #pragma unroll
            for (int bb = 0; bb < 8; bb++)
                #pragma unroll
                for (int cix = 0; cix < 4; cix++) acc[a][bb][cix] = 0.f;

        for (int ch = 0; ch < 32; ch++) {
            if (ch < 31) CP_WAIT1(); else CP_WAIT0();
            __syncthreads();             // publishes stA[ch&1] + W(ch); retires W(ch-1)
            if (ch + 2 < 32) ISSUE_W(ch + 2);   // stage (ch+2)%3: disjoint from read stage
            float v[4];
            if (ch < 31) LDG_A(ch + 1, v);

            const float4* W4 = (const float4*)(dyn + 65536 + (ch % 3) * 16384);
            uint32_t aH[2][4], aL[2][4];
            #pragma unroll
            for (int mt = 0; mt < 2; mt++) {
                int tmg = wm * 2 + mt;
                float4 h4 = stA4[(ch & 1) * 256 + tmg * 32 + lane];
                float4 l4 = stA4[(ch & 1) * 256 + 128 + tmg * 32 + lane];
                aH[mt][0] = __float_as_uint(h4.x); aH[mt][1] = __float_as_uint(h4.y);
                aH[mt][2] = __float_as_uint(h4.z); aH[mt][3] = __float_as_uint(h4.w);
                aL[mt][0] = __float_as_uint(l4.x); aL[mt][1] = __float_as_uint(l4.y);
                aL[mt][2] = __float_as_uint(l4.z); aL[mt][3] = __float_as_uint(l4.w);
            }
            #pragma unroll
            for (int nt = 0; nt < 8; nt++) {
                int tng = wn * 8 + nt;
                float4 bf = W4[tng * 32 + lane];
                uint32_t bh0 = __float_as_uint(bf.x), bh1 = __float_as_uint(bf.y);
                uint32_t bl0 = __float_as_uint(bf.z), bl1 = __float_as_uint(bf.w);
                #pragma unroll
                for (int mt = 0; mt < 2; mt++) {
                    mmaf16(acc[mt][nt], aH[mt][0], aH[mt][1], aH[mt][2], aH[mt][3], bh0, bh1);
                    mmaf16(acc[mt][nt], aH[mt][0], aH[mt][1], aH[mt][2], aH[mt][3], bl0, bl1);
                    mmaf16(acc[mt][nt], aL[mt][0], aL[mt][1], aL[mt][2], aL[mt][3], bh0, bh1);
                }
            }
            if (ch < 31) STS_A((ch + 1) & 1, v);
        }

        // epilogue: bias, ||x||^2, x fragments -> smem A region [0,64K)
        __syncthreads();                 // all stA/W reads retired; A region writable
        float4* xf4 = (float4*)dyn;
        #pragma unroll
        for (int mt = 0; mt < 2; mt++) {
            int tmg = wm * 2 + mt;
            float xnq = 0.f, xnq8 = 0.f;
            #pragma unroll
            for (int ntp = 0; ntp < 4; ntp++) {   // nt pairs (even, odd)
                int ntE = ntp * 2, ntO = ntp * 2 + 1;
                int eE = wn * 64 + ntE * 8 + 2 * kq;
                int eO = wn * 64 + ntO * 8 + 2 * kq;
                float bE0 = __ldg(&bias[eE]),     bE1 = __ldg(&bias[eE + 1]);
                float bO0 = __ldg(&bias[eO]),     bO1 = __ldg(&bias[eO + 1]);
                float x0 = acc[mt][ntE][0] + bE0;
                float x1 = acc[mt][ntE][1] + bE1;
                float x2 = acc[mt][ntE][2] + bE0;
                float x3 = acc[mt][ntE][3] + bE1;
                float y0 = acc[mt][ntO][0] + bO0;
                float y1 = acc[mt][ntO][1] + bO1;
                float y2 = acc[mt][ntO][2] + bO0;
                float y3 = acc[mt][ntO][3] + bO1;
                xnq  += x0 * x0 + x1 * x1 + y0 * y0 + y1 * y1;
                xnq8 += x2 * x2 + x3 * x3 + y2 * y2 + y3 * y3;
                int ks = wn * 4 + ntp;
                uint32_t l0, l1, l2, l3;
                uint32_t h0 = packsplit(x0, x1, l0);
                uint32_t h1 = packsplit(x2, x3, l1);
                uint32_t h2 = packsplit(y0, y1, l2);
                uint32_t h3 = packsplit(y2, y3, l3);
                int idx = (ks * 4 + tmg) * 32 + lane;
                xf4[idx]        = make_float4(__uint_as_float(h0), __uint_as_float(h1),
                                              __uint_as_float(h2), __uint_as_float(h3));
                xf4[2048 + idx] = make_float4(__uint_as_float(l0), __uint_as_float(l1),
                                              __uint_as_float(l2), __uint_as_float(l3));
            }
            xnq  += __shfl_xor_sync(0xffffffffu, xnq, 1);
            xnq  += __shfl_xor_sync(0xffffffffu, xnq, 2);
            xnq8 += __shfl_xor_sync(0xffffffffu, xnq8, 1);
            xnq8 += __shfl_xor_sync(0xffffffffu, xnq8, 2);
            if (kq == 0) {
                int tl = wm * 32 + mt * 16 + q;
                atomicAdd(&sXn[tl], xnq);
                atomicAdd(&sXn[tl + 8], xnq8);
            }
        }
    }

    // ================= PHASE 2: distance + argmin =================
    const float4* smA = (const float4*)dyn;

    #define ISSUE(cc) do {                                                        \
        int _cgp = (cc) >> 4, _ks = (cc) & 15;                                    \
        const char* _s = (const char*)((const float4*)g_ef +                      \
                          ((size_t)(_cgp * 16 + _ks)) * 1024);                    \
        uint32_t _d = ringu + (uint32_t)((cc) % 3) * 16384;                       \
        for (int i = tid; i < 1024; i += 256)                                     \
            cp16(_d + (uint32_t)i * 16, _s + (size_t)i * 16);                     \
        CP_COMMIT();                                                              \
    } while (0)

    ISSUE(0);
    ISSUE(1);

    float acc[2][8][4];
    #pragma unroll
    for (int a = 0; a < 2; a++)
        #pragma unroll
        for (int b2 = 0; b2 < 8; b2++)
            #pragma unroll
            for (int c = 0; c < 4; c++) acc[a][b2][c] = 0.f;
    float bestv[4]; int besti[4];
    #pragma unroll
    for (int s = 0; s < 4; s++) { bestv[s] = 3.0e38f; besti[s] = 0; }

    for (int cc = 0; cc < 64; cc++) {
        if (cc + 1 < 64) CP_WAIT1(); else CP_WAIT0();
        __syncthreads();                 // publishes buf[cc] (+A frags on cc==0)
        if (cc + 2 < 64) ISSUE(cc + 2);
        const float4* B4 = (const float4*)(dyn + 65536 + (cc % 3) * 16384);
        int ks = cc & 15;
        uint32_t aH[2][4], aL[2][4];
        #pragma unroll
        for (int tm2 = 0; tm2 < 2; tm2++) {
            int tmg = wm * 2 + tm2;
            float4 h4 = smA[(ks * 4 + tmg) * 32 + lane];
            float4 l4 = smA[2048 + (ks * 4 + tmg) * 32 + lane];
            aH[tm2][0] = __float_as_uint(h4.x); aH[tm2][1] = __float_as_uint(h4.y);
            aH[tm2][2] = __float_as_uint(h4.z); aH[tm2][3] = __float_as_uint(h4.w);
            aL[tm2][0] = __float_as_uint(l4.x); aL[tm2][1] = __float_as_uint(l4.y);
            aL[tm2][2] = __float_as_uint(l4.z); aL[tm2][3] = __float_as_uint(l4.w);
        }
        #pragma unroll
        for (int tn = 0; tn < 8; tn++) {
            int tng = wn * 8 + tn;
            float4 bf = B4[tng * 32 + lane];
            uint32_t bh0 = __float_as_uint(bf.x), bh1 = __float_as_uint(bf.y);
            uint32_t bl0 = __float_as_uint(bf.z), bl1 = __float_as_uint(bf.w);
            #pragma unroll
            for (int tm2 = 0; tm2 < 2; tm2++) {
                mmaf16(acc[tm2][tn], aH[tm2][0], aH[tm2][1], aH[tm2][2], aH[tm2][3], bh0, bh1);
                mmaf16(acc[tm2][tn], aH[tm2][0], aH[tm2][1], aH[tm2][2], aH[tm2][3], bl0, bl1);
                mmaf16(acc[tm2][tn], aL[tm2][0], aL[tm2][1], aL[tm2][2], aL[tm2][3], bh0, bh1);
            }
        }
        if (ks == 15) {
            int cgp = cc >> 4;
            #pragma unroll
            for (int tn = 0; tn < 8; tn++) {
                int tng = wn * 8 + tn;
                int nb = cgp * 256 + tng * 8 + 2 * kq;
                float e0v = __ldg(&g_enorm[nb]);
                float e1v = __ldg(&g_enorm[nb + 1]);
                #pragma unroll
                for (int tm2 = 0; tm2 < 2; tm2++) {
                    float s00 = fmaf(-2.0f, acc[tm2][tn][0], e0v);
                    float s01 = fmaf(-2.0f, acc[tm2][tn][1], e1v);
                    float s10 = fmaf(-2.0f, acc[tm2][tn][2], e0v);
                    float s11 = fmaf(-2.0f, acc[tm2][tn][3], e1v);
                    int s0 = tm2 * 2, s1 = tm2 * 2 + 1;
                    if (s00 < bestv[s0]) { bestv[s0] = s00; besti[s0] = nb; }
                    if (s01 < bestv[s0]) { bestv[s0] = s01; besti[s0] = nb + 1; }
                    if (s10 < bestv[s1]) { bestv[s1] = s10; besti[s1] = nb; }
                    if (s11 < bestv[s1]) { bestv[s1] = s11; besti[s1] = nb + 1; }
                    acc[tm2][tn][0] = 0.f; acc[tm2][tn][1] = 0.f;
                    acc[tm2][tn][2] = 0.f; acc[tm2][tn][3] = 0.f;
                }
            }
        }
    }
    __syncthreads();                     // compute done; reuse B ring
    float* redv = (float*)(dyn + 65536);            // 64*4 floats
    int*   redi = (int*)(dyn + 65536 + 1024);       // 64*4 ints
    float* lred = (float*)(dyn + 65536 + 2048);     // 2 floats

    #pragma unroll
    for (int s = 0; s < 4; s++) {
        float v = bestv[s]; int bi = besti[s];
        #pragma unroll
        for (int off = 1; off <= 2; off <<= 1) {
            float ov = __shfl_xor_sync(0xffffffffu, v, off);
            int   oi = __shfl_xor_sync(0xffffffffu, bi, off);
            if (ov < v || (ov == v && oi < bi)) { v = ov; bi = oi; }
        }
        if ((lane & 3) == 0) {
            int row = wm * 32 + (s >> 1) * 16 + (s & 1) * 8 + q;
            redv[row * 4 + wn] = v;
            redi[row * 4 + wn] = bi;
        }
    }
    __syncthreads();
    float myd2 = 0.f;
    if (tid < 64) {
        float v = redv[tid * 4]; int bi = redi[tid * 4];
        #pragma unroll
        for (int j = 1; j < 4; j++) {
            float ov = redv[tid * 4 + j]; int oi = redi[tid * 4 + j];
            if (ov < v || (ov == v && oi < bi)) { v = ov; bi = oi; }
        }
        int n = n0 + tid;
        g_idx[n] = bi;
        atomicAdd(&g_hist[bi], 1);
        myd2 = sXn[tid] + v;                   // ||x||^2 + (||e||^2 - 2x.e)
    }
    for (int o = 16; o > 0; o >>= 1) myd2 += __shfl_down_sync(0xffffffffu, myd2, o);
    if ((tid & 31) == 0 && wid < 2) lred[wid] = myd2;
    __syncthreads();
    if (tid == 0) atomicAdd(&g_mse, (double)(lred[0] + lred[1]));
}

// ---------------------------------------------------------------
// output: z_q_out[b,e,t] = embed[q_idx[b*T+t]][e]  (32x32 transpose)
// ---------------------------------------------------------------
__global__ void k_out(const float* __restrict__ embed, float* __restrict__ out) {
    __shared__ int   qs[32];
    __shared__ float sm[32][33];
    int b  = blockIdx.z;
    int e0 = blockIdx.y * 32;
    int t0 = blockIdx.x * 32;
    int tid = threadIdx.x;
    if (tid < 32) qs[tid] = g_idx[b * Tt + t0 + tid];
    __syncthreads();
    {
        int j = tid >> 3, gg = tid & 7;
        const float4* erow = (const float4*)(embed + (size_t)qs[j] * Ee + e0);
        float4 v = erow[gg];
        sm[j][gg * 4 + 0] = v.x; sm[j][gg * 4 + 1] = v.y;
        sm[j][gg * 4 + 2] = v.z; sm[j][gg * 4 + 3] = v.w;
    }
    __syncthreads();
    int tl = tid & 31, eb = tid >> 5;
    #pragma unroll
    for (int r = 0; r < 4; r++) {
        int el = eb + r * 8;
        out[((size_t)b * Ee + e0 + el) * Tt + t0 + tl] = sm[tl][el];
    }
}

// ---------------------------------------------------------------
// tail scalars
// ---------------------------------------------------------------
__global__ void k_tail(float* __restrict__ out) {
    __shared__ float red[32];
    int tid = threadIdx.x;                     // 1024
    float p = (float)g_hist[tid] / 65536.0f;
    float term = -p * logf(p + 1e-10f);
    for (int o = 16; o > 0; o >>= 1) term += __shfl_down_sync(0xffffffffu, term, o);
    if ((tid & 31) == 0) red[tid >> 5] = term;
    __syncthreads();
    const size_t base = (size_t)Bb * Ee * Tt;
    if (tid == 0) {
        float lp = 0.f;
        #pragma unroll
        for (int i = 0; i < 32; i++) lp += red[i];
        out[base + 0]  = (float)(1.25 * (g_mse / (double)((size_t)NTOK * Ee)));
        out[base + 17] = lp;
    }
    if (tid < 16) out[base + 1 + tid] = (float)(log(1024.0) * 4096.0);
}

// ---------------------------------------------------------------
extern "C" void kernel_launch(void* const* d_in, const int* in_sizes, int n_in,
                              void* d_out, int out_size) {
    const float* inputs = (const float*)d_in[0];   // [16, 512, 4096]
    const float* proj_w = (const float*)d_in[1];   // [256, 512]
    const float* proj_b = (const float*)d_in[2];   // [256]
    const float* embed  = (const float*)d_in[3];   // [1024, 256]
    float* out = (float*)d_out;

    cudaFuncSetAttribute(k_main, cudaFuncAttributeMaxDynamicSharedMemorySize, MAIN_DYN);

    k_prep<<<NE + Cc, 256>>>(embed, proj_w);
    k_main<<<NTOK / 64, 256, MAIN_DYN>>>(inputs, proj_b);
    dim3 g3(Tt / 32, Ee / 32, Bb);
    k_out<<<g3, 256>>>(embed, out);
    k_tail<<<1, 1024>>>(out);
}